// round 16
// baseline (speedup 1.0000x reference)
#include <cuda_runtime.h>
#include <cuda_bf16.h>
#include <math.h>

#define BB   64
#define SS   512
#define EE   128
#define HH   128
#define GG   512          // 4*H
#define FWW  6
#define WW   507          // S - FW + 1
#define MT   32           // windows per CLUSTER (both ranks share rows, split cols)
#define NTHREADS 128
#define NCL  (16*BB)      // 1024 clusters (16 tiles/row)
#define NCTAS (2*NCL)     // 2048 CTAs

// smem layout (per CTA): w slice 64K | emb 12K | A0 8K | A1 8K | X 19.5K
#define XSTR   528
#define OFF_W   0
#define OFF_EMB 65536
#define OFF_A0  77824
#define OFF_A1  86016
#define OFF_X   94208
#define X_ROWS  37
#define SMEM_L  (OFF_X + X_ROWS*XSTR)   // 113744 -> 2 CTAs/SM

// Scratch (device globals: allocation is forbidden)
__device__ __align__(16) __nv_bfloat16 g_wih16[GG * EE];
__device__ __align__(16) __nv_bfloat16 g_whh16[GG * HH];
__device__ unsigned g_featu[BB * HH];   // order-encoded float, atomicMax pooling
__device__ unsigned g_done;             // CTA completion counter

// ---------------------------------------------------------------------------
__device__ __forceinline__ unsigned sptr(const void* p) {
    return (unsigned)__cvta_generic_to_shared(p);
}
__device__ __forceinline__ float tanha_(float x) {
    float y; asm("tanh.approx.f32 %0, %1;" : "=f"(y) : "f"(x)); return y;
}
__device__ __forceinline__ float sigm_(float x) {
    return fmaf(0.5f, tanha_(0.5f * x), 0.5f);
}
__device__ __forceinline__ unsigned encf_(float x) {
    unsigned u = __float_as_uint(x);
    return (u & 0x80000000u) ? ~u : (u | 0x80000000u);
}
__device__ __forceinline__ float decf_(unsigned k) {
    return __uint_as_float((k & 0x80000000u) ? (k & 0x7fffffffu) : ~k);
}
__device__ __forceinline__ void ldsm4(unsigned* r, unsigned addr) {
    asm volatile("ldmatrix.sync.aligned.m8n8.x4.shared.b16 {%0,%1,%2,%3}, [%4];"
                 : "=r"(r[0]), "=r"(r[1]), "=r"(r[2]), "=r"(r[3]) : "r"(addr));
}
__device__ __forceinline__ void mma_bf16(float* d, const unsigned* a, unsigned b0, unsigned b1) {
    asm("mma.sync.aligned.m16n8k16.row.col.f32.bf16.bf16.f32 "
        "{%0,%1,%2,%3},{%4,%5,%6,%7},{%8,%9},{%0,%1,%2,%3};"
        : "+f"(d[0]), "+f"(d[1]), "+f"(d[2]), "+f"(d[3])
        : "r"(a[0]), "r"(a[1]), "r"(a[2]), "r"(a[3]), "r"(b0), "r"(b1));
}
__device__ __forceinline__ unsigned packbf2(float lo, float hi) {
    __nv_bfloat162 p = __float22bfloat162_rn(make_float2(lo, hi));
    return *reinterpret_cast<unsigned*>(&p);
}
__device__ __forceinline__ float2 unpackbf2(unsigned u) {
    return __bfloat1622float2(*reinterpret_cast<__nv_bfloat162*>(&u));
}
__device__ __forceinline__ unsigned ctarank_() {
    unsigned r; asm("mov.u32 %0, %%cluster_ctarank;" : "=r"(r)); return r;
}
__device__ __forceinline__ void st_cluster32(unsigned laddr, unsigned rank, unsigned val) {
    unsigned ra;
    asm volatile("mapa.shared::cluster.u32 %0, %1, %2;" : "=r"(ra) : "r"(laddr), "r"(rank));
    asm volatile("st.shared::cluster.u32 [%0], %1;" :: "r"(ra), "r"(val) : "memory");
}
#define CLUSTER_SYNC() do { \
    asm volatile("barrier.cluster.arrive.aligned;" ::: "memory"); \
    asm volatile("barrier.cluster.wait.aligned;" ::: "memory"); \
} while (0)

// ---------------------------------------------------------------------------
__global__ void prep_kernel(const float* __restrict__ w_ih, const float* __restrict__ w_hh) {
    int i = blockIdx.x * blockDim.x + threadIdx.x;
    if (i < GG * EE) {
        g_wih16[i] = __float2bfloat16(w_ih[i]);
        g_whh16[i] = __float2bfloat16(w_hh[i]);
    }
    if (i < BB * HH) g_featu[i] = 0u;
    if (i == 0) g_done = 0u;
}

// ---------------------------------------------------------------------------
// Stage this rank's 256-gate-row slice of a weight matrix, 16B-swizzled.
// Local row L = gs*64 + j  ->  global row gs*128 + 64*rank + j.
// ---------------------------------------------------------------------------
__device__ __forceinline__ void stage_slice(const __nv_bfloat16* __restrict__ src,
                                            char* w_sc, int tid, int rank) {
    const uint4* s = (const uint4*)src;
    uint4* d = (uint4*)w_sc;
    #pragma unroll
    for (int i = 0; i < 32; ++i) {
        int id = i * 128 + tid;
        int L  = id >> 4, c = id & 15;
        int gr = (L >> 6) * 128 + 64 * rank + (L & 63);
        d[L * 16 + (c ^ (L & 7))] = s[gr * 16 + c];
    }
}

// ---------------------------------------------------------------------------
// Fused cluster kernel
// ---------------------------------------------------------------------------
__global__ __launch_bounds__(NTHREADS, 2) __cluster_dims__(2, 1, 1)
void lstm_kernel(const int* __restrict__ inputs,
                 const float* __restrict__ embed,
                 const float* __restrict__ b_ih,
                 const float* __restrict__ b_hh,
                 const float* __restrict__ fc_w,
                 const float* __restrict__ fc_b,
                 float* __restrict__ out)
{
    extern __shared__ char smem[];
    char* w_sc  = smem + OFF_W;
    char* e_sc  = smem + OFF_EMB;
    char* a0_sc = smem + OFF_A0;
    char* x_sc  = smem + OFF_X;

    const int tid  = threadIdx.x;
    const int lane = tid & 31;
    const int wid  = tid >> 5;
    const int g    = lane >> 2;
    const int tq   = lane & 3;
    const int rs   = lane & 7;
    const int qb   = (lane >> 3) & 1;
    const int qh   = (lane >> 4) & 1;
    const int nw0l = wid * 16;               // warp's 16-col slice within the 64-col block

    const int rank = (int)ctarank_();
    const int cl   = blockIdx.x >> 1;
    const int b    = cl >> 4;
    const int w0   = (cl & 15) * MT;
    const int wlim = WW - w0;
    const int col0 = 64 * rank + nw0l;       // global h-col base for this warp

    // ---- stage w_ih slice + emb rows 0..47 ----
    stage_slice(g_wih16, w_sc, tid, rank);
    #pragma unroll
    for (int i = 0; i < 6; ++i) {
        int id = i * 128 + tid;
        int row = id >> 4, c = id & 15;
        int tok = min(w0 + row, SS - 1);
        const float4* erow = (const float4*)(embed + (size_t)inputs[b * SS + tok] * EE);
        float4 v0 = erow[2 * c], v1 = erow[2 * c + 1];
        uint4 u;
        u.x = packbf2(v0.x, v0.y); u.y = packbf2(v0.z, v0.w);
        u.z = packbf2(v1.x, v1.y); u.w = packbf2(v1.z, v1.w);
        *(uint4*)(e_sc + row * 256 + ((c ^ (row & 7)) << 4)) = u;
    }

    float bias[4][2][2];
    #pragma unroll
    for (int gs = 0; gs < 4; ++gs)
        #pragma unroll
        for (int nt = 0; nt < 2; ++nt) {
            int colg = gs * 128 + col0 + nt * 8 + 2 * tq;
            float2 bi = *(const float2*)&b_ih[colg];
            float2 bh = *(const float2*)&b_hh[colg];
            bias[gs][nt][0] = bi.x + bh.x;
            bias[gs][nt][1] = bi.y + bh.y;
        }

    const unsigned wS = sptr(w_sc);
    const unsigned eS = sptr(e_sc);
    const unsigned bB = wS + (nw0l + rs + 8 * qh) * 256;   // chunk stride 16384

    __syncthreads();   // w_ih + emb staged

    // ---- X slice = emb @ w_ih_slice^T + bias (rows 0..47, store <37) ----
    {
        float accx[4][3][2][4];
        #pragma unroll
        for (int gs = 0; gs < 4; ++gs)
            #pragma unroll
            for (int mt = 0; mt < 3; ++mt)
                #pragma unroll
                for (int nt = 0; nt < 2; ++nt) {
                    accx[gs][mt][nt][0] = bias[gs][nt][0]; accx[gs][mt][nt][1] = bias[gs][nt][1];
                    accx[gs][mt][nt][2] = bias[gs][nt][0]; accx[gs][mt][nt][3] = bias[gs][nt][1];
                }
        unsigned aP = eS + (rs + 8 * qb) * 256;
        #pragma unroll
        for (int ks = 0; ks < 8; ++ks) {
            unsigned af[3][4];
            unsigned ca = ((unsigned)((2 * ks + qh) ^ rs)) << 4;
            #pragma unroll
            for (int mt = 0; mt < 3; ++mt) ldsm4(af[mt], aP + mt * 4096 + ca);
            unsigned cb = ((unsigned)((2 * ks + qb) ^ rs)) << 4;
            #pragma unroll
            for (int gs = 0; gs < 4; ++gs) {
                unsigned bf[4];
                ldsm4(bf, bB + gs * 16384 + cb);
                #pragma unroll
                for (int mt = 0; mt < 3; ++mt) {
                    mma_bf16(accx[gs][mt][0], af[mt], bf[0], bf[1]);
                    mma_bf16(accx[gs][mt][1], af[mt], bf[2], bf[3]);
                }
            }
        }
        #pragma unroll
        for (int mt = 0; mt < 3; ++mt)
            #pragma unroll
            for (int hh = 0; hh < 2; ++hh) {
                int r = mt * 16 + g + 8 * hh;
                if (r < X_ROWS) {
                    #pragma unroll
                    for (int gs = 0; gs < 4; ++gs)
                        #pragma unroll
                        for (int nt = 0; nt < 2; ++nt) {
                            int lc = gs * 64 + nw0l + nt * 8 + 2 * tq;
                            *(unsigned*)(x_sc + r * XSTR + lc * 2) =
                                packbf2(accx[gs][mt][nt][2 * hh], accx[gs][mt][nt][2 * hh + 1]);
                        }
                }
            }
    }

    __syncthreads();                       // X written; w_ih reads done
    stage_slice(g_whh16, w_sc, tid, rank); // W := w_hh slice
    __syncthreads();

    // ---- recurrence ----
    float acc[4][2][2][4];
    float c_st[2][2][4] = {};
    float hreg[2][2][4];
    float pmax[2][2] = {{-3.4e38f, -3.4e38f}, {-3.4e38f, -3.4e38f}};
    const unsigned aA[2] = { sptr(a0_sc) + (rs + 8 * qb) * 256,
                             sptr(a0_sc) + 8192 + (rs + 8 * qb) * 256 };
    const int cb0base = col0 >> 3;

    for (int t = 0; t < FWW; ++t) {
        // acc = X(t)
        #pragma unroll
        for (int mt = 0; mt < 2; ++mt)
            #pragma unroll
            for (int hh = 0; hh < 2; ++hh) {
                int r = t + mt * 16 + g + 8 * hh;
                #pragma unroll
                for (int gs = 0; gs < 4; ++gs)
                    #pragma unroll
                    for (int nt = 0; nt < 2; ++nt) {
                        int lc = gs * 64 + nw0l + nt * 8 + 2 * tq;
                        float2 v = unpackbf2(*(const unsigned*)(x_sc + r * XSTR + lc * 2));
                        acc[gs][mt][nt][2 * hh]     = v.x;
                        acc[gs][mt][nt][2 * hh + 1] = v.y;
                    }
            }

        if (t > 0) {
            unsigned aB0 = aA[(t - 1) & 1];
            #pragma unroll
            for (int ks = 0; ks < 8; ++ks) {
                unsigned af0[4], af1[4];
                unsigned ca = ((unsigned)((2 * ks + qh) ^ rs)) << 4;
                ldsm4(af0, aB0 + ca);
                ldsm4(af1, aB0 + 4096 + ca);
                unsigned cb = ((unsigned)((2 * ks + qb) ^ rs)) << 4;
                #pragma unroll
                for (int gs = 0; gs < 4; ++gs) {
                    unsigned bf[4];
                    ldsm4(bf, bB + gs * 16384 + cb);
                    mma_bf16(acc[gs][0][0], af0, bf[0], bf[1]);
                    mma_bf16(acc[gs][0][1], af0, bf[2], bf[3]);
                    mma_bf16(acc[gs][1][0], af1, bf[0], bf[1]);
                    mma_bf16(acc[gs][1][1], af1, bf[2], bf[3]);
                }
            }
        }

        // cell
        #pragma unroll
        for (int mt = 0; mt < 2; ++mt)
            #pragma unroll
            for (int nt = 0; nt < 2; ++nt)
                #pragma unroll
                for (int q = 0; q < 4; ++q) {
                    float gi = acc[0][mt][nt][q], gf = acc[1][mt][nt][q];
                    float gg = acc[2][mt][nt][q], go = acc[3][mt][nt][q];
                    float cn = sigm_(gf) * c_st[mt][nt][q] + sigm_(gi) * tanha_(gg);
                    c_st[mt][nt][q] = cn;
                    hreg[mt][nt][q] = sigm_(go) * tanha_(cn);
                }

        if (t < FWW - 1) {
            // store h to own + peer A buffer (ping-pong t&1), then cluster barrier
            unsigned abuf = sptr(a0_sc) + (unsigned)((t & 1) * 8192);
            #pragma unroll
            for (int mt = 0; mt < 2; ++mt)
                #pragma unroll
                for (int nt = 0; nt < 2; ++nt)
                    #pragma unroll
                    for (int hh = 0; hh < 2; ++hh) {
                        int r_ = mt * 16 + g + 8 * hh;
                        int cb_ = cb0base + nt;
                        unsigned addr = abuf + r_ * 256 + (((unsigned)(cb_ ^ g)) << 4) + 4 * tq;
                        unsigned val = packbf2(hreg[mt][nt][2 * hh], hreg[mt][nt][2 * hh + 1]);
                        asm volatile("st.shared.b32 [%0], %1;" :: "r"(addr), "r"(val) : "memory");
                        st_cluster32(addr, (unsigned)(rank ^ 1), val);
                    }
            CLUSTER_SYNC();
        } else {
            #pragma unroll
            for (int mt = 0; mt < 2; ++mt)
                #pragma unroll
                for (int nt = 0; nt < 2; ++nt)
                    #pragma unroll
                    for (int hh = 0; hh < 2; ++hh) {
                        if (mt * 16 + g + 8 * hh < wlim) {
                            pmax[nt][0] = fmaxf(pmax[nt][0], hreg[mt][nt][2 * hh]);
                            pmax[nt][1] = fmaxf(pmax[nt][1], hreg[mt][nt][2 * hh + 1]);
                        }
                    }
        }
    }

    // ---- pool: shfl over rows (g), one atomicMax per owned column ----
    #pragma unroll
    for (int nt = 0; nt < 2; ++nt)
        #pragma unroll
        for (int e = 0; e < 2; ++e) {
            float m = pmax[nt][e];
            m = fmaxf(m, __shfl_xor_sync(0xffffffffu, m, 4));
            m = fmaxf(m, __shfl_xor_sync(0xffffffffu, m, 8));
            m = fmaxf(m, __shfl_xor_sync(0xffffffffu, m, 16));
            pmax[nt][e] = m;
        }
    if (g == 0) {
        #pragma unroll
        for (int nt = 0; nt < 2; ++nt)
            #pragma unroll
            for (int e = 0; e < 2; ++e)
                atomicMax(&g_featu[b * HH + col0 + nt * 8 + 2 * tq + e], encf_(pmax[nt][e]));
    }

    // ---- last CTA computes the FC ----
    __threadfence();
    __shared__ unsigned s_last;
    if (tid == 0) {
        unsigned old = atomicAdd(&g_done, 1u);
        s_last = (old == (unsigned)(NCTAS - 1)) ? 1u : 0u;
    }
    __syncthreads();
    if (s_last) {
        int fb = tid >> 1;            // batch
        int o  = tid & 1;             // output class
        float s = fc_b[o];
        #pragma unroll 8
        for (int k = 0; k < HH; ++k) {
            unsigned enc = atomicAdd(&g_featu[fb * HH + k], 0u);   // coherent read
            s += decf_(enc) * fc_w[o * HH + k];
        }
        out[fb * 2 + o] = s;
    }
}

// ---------------------------------------------------------------------------
extern "C" void kernel_launch(void* const* d_in, const int* in_sizes, int n_in,
                              void* d_out, int out_size)
{
    const int*   inputs = (const int*)  d_in[0];
    // d_in[1] = lengths : unused by the reference
    const float* embed  = (const float*)d_in[2];
    const float* w_ih   = (const float*)d_in[3];
    const float* w_hh   = (const float*)d_in[4];
    const float* b_ih   = (const float*)d_in[5];
    const float* b_hh   = (const float*)d_in[6];
    const float* fc_w   = (const float*)d_in[7];
    const float* fc_b   = (const float*)d_in[8];
    float* out = (float*)d_out;

    cudaFuncSetAttribute(lstm_kernel, cudaFuncAttributeMaxDynamicSharedMemorySize, SMEM_L);

    prep_kernel<<<(GG * EE + 255) / 256, 256>>>(w_ih, w_hh);
    lstm_kernel<<<NCTAS, NTHREADS, SMEM_L>>>(inputs, embed, b_ih, b_hh, fc_w, fc_b, out);
}